// round 3
// baseline (speedup 1.0000x reference)
#include <cuda_runtime.h>

#define T_TREES 20
#define N_INT   31
#define N_LEAF  32
#define F_DIM   128
#define ROWS_PER_CTA 128

// Scratch (allocation-free rule: __device__ globals)
__device__ float g_Wm[T_TREES * N_INT * F_DIM];     // masked split weights
__device__ float g_coef[T_TREES * N_LEAF * 2];      // w_t * softmax(leaf_logits)

// ---------------------------------------------------------------------------
// Prep kernel 1: masked weights. grid = T*N_INT blocks, 128 threads
// ---------------------------------------------------------------------------
__global__ void prep_w_kernel(const float* __restrict__ sw,
                              const float* __restrict__ fm) {
    int tn = blockIdx.x;          // t*N_INT + n
    int t  = tn / N_INT;
    int f  = threadIdx.x;
    g_Wm[tn * F_DIM + f] = sw[tn * F_DIM + f] * fm[t * F_DIM + f];
}

// ---------------------------------------------------------------------------
// Prep kernel 2: tree-weight softmax folded into leaf class softmax.
// 1 block, 32 threads (20 active). Redundant per-thread reductions are fine.
// ---------------------------------------------------------------------------
__global__ void prep_coef_kernel(const float* __restrict__ ll,
                                 const float* __restrict__ tw) {
    int t = threadIdx.x;
    if (t >= T_TREES) return;
    float mx = tw[0];
    for (int i = 1; i < T_TREES; ++i) mx = fmaxf(mx, tw[i]);
    float s = 0.f;
    for (int i = 0; i < T_TREES; ++i) s += expf(tw[i] - mx);
    float w = expf(tw[t] - mx) / s;
    for (int l = 0; l < N_LEAF; ++l) {
        float a = ll[(t * N_LEAF + l) * 2 + 0];
        float b = ll[(t * N_LEAF + l) * 2 + 1];
        float m  = fmaxf(a, b);
        float ea = expf(a - m), eb = expf(b - m);
        float inv = 1.f / (ea + eb);
        g_coef[(t * N_LEAF + l) * 2 + 0] = w * ea * inv;
        g_coef[(t * N_LEAF + l) * 2 + 1] = w * eb * inv;
    }
}

// ---------------------------------------------------------------------------
// Main fused kernel: one thread per batch row, loop over trees.
//   Phase A per tree: 31 dot products (x in regs, W broadcast from smem),
//                     sigmoid -> smem sG (stride-31 => bank-conflict-free).
//   Phase B per tree: bottom-up subtree combine folding leaf class coefs:
//                     B(k) = B_left + g_k * (B_right - B_left)
// ---------------------------------------------------------------------------
__global__ __launch_bounds__(128, 2)
void forest_kernel(const float* __restrict__ x,
                   const float* __restrict__ bias,
                   float* __restrict__ out) {
    __shared__ float4 sW[N_INT * (F_DIM / 4)];        // 15.875 KB
    __shared__ float  sG[ROWS_PER_CTA * N_INT];       // 15.875 KB
    __shared__ float  sBias[N_INT];
    __shared__ float  sCoef[N_LEAF * 2];

    const int r = threadIdx.x;
    const long row = (long)blockIdx.x * ROWS_PER_CTA + r;

    // x row -> registers (512B per lane, lines fully consumed, MLP=32)
    float4 xv[F_DIM / 4];
    const float4* xg = (const float4*)(x + row * F_DIM);
#pragma unroll
    for (int i = 0; i < F_DIM / 4; ++i) xv[i] = xg[i];

    float acc0 = 0.f, acc1 = 0.f;

    for (int t = 0; t < T_TREES; ++t) {
        __syncthreads();   // protect sW/sBias/sCoef reuse across trees
        {
            const float4* wsrc = (const float4*)(g_Wm + t * N_INT * F_DIM);
            for (int i = r; i < N_INT * (F_DIM / 4); i += 128) sW[i] = wsrc[i];
            if (r < N_INT)     sBias[r] = bias[t * N_INT + r];
            if (r < N_LEAF*2)  sCoef[r] = g_coef[t * N_LEAF * 2 + r];
        }
        __syncthreads();

        // -------- Phase A: logits + sigmoid --------
        for (int n = 0; n < N_INT; ++n) {
            float a0 = 0.f, a1 = 0.f, a2 = 0.f, a3 = 0.f;
#pragma unroll
            for (int i = 0; i < F_DIM / 4; ++i) {
                float4 w = sW[n * (F_DIM / 4) + i];   // broadcast LDS.128
                a0 += xv[i].x * w.x;
                a1 += xv[i].y * w.y;
                a2 += xv[i].z * w.z;
                a3 += xv[i].w * w.w;
            }
            float z = (a0 + a1) + (a2 + a3) + sBias[n];
            float g = 1.f / (1.f + __expf(-z));
            sG[r * N_INT + n] = g;                    // (n - r) % 32: no conflicts
        }

        // -------- Phase B: bottom-up combine --------
        const float* gRow = sG + r * N_INT;
        float b0[16], b1[16];
#pragma unroll
        for (int i = 0; i < 16; ++i) {                // level 4: nodes 15..30
            float g   = gRow[15 + i];
            float c0l = sCoef[(2 * i) * 2 + 0], c1l = sCoef[(2 * i) * 2 + 1];
            float c0r = sCoef[(2 * i + 1) * 2 + 0], c1r = sCoef[(2 * i + 1) * 2 + 1];
            b0[i] = c0l + g * (c0r - c0l);
            b1[i] = c1l + g * (c1r - c1l);
        }
#pragma unroll
        for (int i = 0; i < 8; ++i) {                 // level 3: nodes 7..14
            float g = gRow[7 + i];
            b0[i] = b0[2 * i] + g * (b0[2 * i + 1] - b0[2 * i]);
            b1[i] = b1[2 * i] + g * (b1[2 * i + 1] - b1[2 * i]);
        }
#pragma unroll
        for (int i = 0; i < 4; ++i) {                 // level 2: nodes 3..6
            float g = gRow[3 + i];
            b0[i] = b0[2 * i] + g * (b0[2 * i + 1] - b0[2 * i]);
            b1[i] = b1[2 * i] + g * (b1[2 * i + 1] - b1[2 * i]);
        }
#pragma unroll
        for (int i = 0; i < 2; ++i) {                 // level 1: nodes 1..2
            float g = gRow[1 + i];
            b0[i] = b0[2 * i] + g * (b0[2 * i + 1] - b0[2 * i]);
            b1[i] = b1[2 * i] + g * (b1[2 * i + 1] - b1[2 * i]);
        }
        {                                             // level 0: root
            float g = gRow[0];
            acc0 += b0[0] + g * (b0[1] - b0[0]);
            acc1 += b1[0] + g * (b1[1] - b1[0]);
        }
    }

    out[row * 2 + 0] = acc0;
    out[row * 2 + 1] = acc1;
}

// ---------------------------------------------------------------------------
// metadata order: x, split_weights, split_bias, leaf_logits, tree_weights,
//                 feature_masks.  output: [B,2] float32
// ---------------------------------------------------------------------------
extern "C" void kernel_launch(void* const* d_in, const int* in_sizes, int n_in,
                              void* d_out, int out_size) {
    const float* x  = (const float*)d_in[0];
    const float* sw = (const float*)d_in[1];
    const float* sb = (const float*)d_in[2];
    const float* ll = (const float*)d_in[3];
    const float* tw = (const float*)d_in[4];
    const float* fm = (const float*)d_in[5];
    float* out = (float*)d_out;

    const int B = in_sizes[0] / F_DIM;   // 131072

    prep_w_kernel<<<T_TREES * N_INT, F_DIM>>>(sw, fm);
    prep_coef_kernel<<<1, 32>>>(ll, tw);
    forest_kernel<<<B / ROWS_PER_CTA, ROWS_PER_CTA>>>(x, sb, out);
}

// round 8
// speedup vs baseline: 7.7401x; 7.7401x over previous
#include <cuda_runtime.h>
#include <cuda_bf16.h>
#include <cstdint>

#define T_TREES 20
#define N_INT   31
#define F_DIM   128
#define TILE_M  256
#define THREADS 256

// ---------------- smem layout (bytes) ----------------
#define B_STRIDE 272                       // 128 bf16 = 256B + 16B pad (ldmatrix conflict-free)
#define B_TREE   (32 * B_STRIDE)           // 8704 per tree
#define SM_B     0
#define SM_G     (T_TREES * B_TREE)                  // 174080
#define G_STRIDE 260                                 // words: 256 rows + 4 pad (S%32==4)
#define SM_HB    (SM_G + 32 * G_STRIDE * 4)          // 207360
#define SM_COEF  (SM_HB + T_TREES * 32 * 4)          // 209920
#define SMEM_TOTAL (SM_COEF + T_TREES * 16 * 16)     // 215040

__device__ __forceinline__ uint32_t smem_u32(const void* p) {
    uint32_t a;
    asm("{ .reg .u64 t; cvta.to.shared.u64 t, %1; cvt.u32.u64 %0, t; }" : "=r"(a) : "l"(p));
    return a;
}

// sigmoid(z) = 0.5*tanh(0.5*z + 0.5*bias) + 0.5  -> one MUFU.TANH
__device__ __forceinline__ float sig_half(float logit, float hb) {
    float z = fmaf(logit, 0.5f, hb);
    float th;
    asm("tanh.approx.f32 %0, %1;" : "=f"(th) : "f"(z));
    return fmaf(th, 0.5f, 0.5f);
}

#define LDSM_X4(d0, d1, d2, d3, addr) \
    asm volatile("ldmatrix.sync.aligned.m8n8.x4.shared.b16 {%0,%1,%2,%3}, [%4];" \
                 : "=r"(d0), "=r"(d1), "=r"(d2), "=r"(d3) : "r"(addr))

#define MMA_16816(c, a, b0v, b1v) \
    asm volatile("mma.sync.aligned.m16n8k16.row.col.f32.bf16.bf16.f32 " \
                 "{%0,%1,%2,%3}, {%4,%5,%6,%7}, {%8,%9}, {%0,%1,%2,%3};" \
                 : "+f"((c)[0]), "+f"((c)[1]), "+f"((c)[2]), "+f"((c)[3]) \
                 : "r"((a)[0]), "r"((a)[1]), "r"((a)[2]), "r"((a)[3]), \
                   "r"(b0v), "r"(b1v))

// ---------------------------------------------------------------------------
// One persistent kernel. CTA init builds all per-model tables in smem
// (no prep launches: each ~4us of pure launch overhead per R3 profile).
// ---------------------------------------------------------------------------
__global__ __launch_bounds__(THREADS, 1)
void forest_hmma(const float* __restrict__ x,  const float* __restrict__ sw,
                 const float* __restrict__ sb, const float* __restrict__ ll,
                 const float* __restrict__ tw, const float* __restrict__ fm,
                 float* __restrict__ out, int n_tiles)
{
    extern __shared__ unsigned char smem[];
    const int tid  = threadIdx.x;
    const int lane = tid & 31;
    const int warp = tid >> 5;

    // ---------- CTA init ----------
    // B tiles: bf16 masked weights, [n][k] row-major, 272B row stride, row 31 zero.
    for (int idx = tid; idx < T_TREES * 32 * F_DIM; idx += THREADS) {
        int t = idx >> 12, n = (idx >> 7) & 31, k = idx & 127;
        float v = (n < N_INT) ? sw[(t * N_INT + n) * F_DIM + k] * fm[t * F_DIM + k] : 0.f;
        *(__nv_bfloat16*)(smem + SM_B + t * B_TREE + n * B_STRIDE + k * 2) = __float2bfloat16(v);
    }
    float* hb = (float*)(smem + SM_HB);
    for (int idx = tid; idx < T_TREES * 32; idx += THREADS) {
        int t = idx >> 5, n = idx & 31;
        hb[idx] = (n < N_INT) ? 0.5f * sb[t * N_INT + n] : 0.f;
    }
    if (tid < T_TREES) {
        int t = tid;
        float mx = tw[0];
        for (int i = 1; i < T_TREES; ++i) mx = fmaxf(mx, tw[i]);
        float s = 0.f;
        for (int i = 0; i < T_TREES; ++i) s += expf(tw[i] - mx);
        float w = expf(tw[t] - mx) / s;
        float4* cf = (float4*)(smem + SM_COEF) + t * 16;
        for (int p = 0; p < 16; ++p) {
            float a0 = ll[(t * 32 + 2 * p) * 2 + 0], b0 = ll[(t * 32 + 2 * p) * 2 + 1];
            float m0 = fmaxf(a0, b0), e0 = expf(a0 - m0), f0 = expf(b0 - m0);
            float i0 = w / (e0 + f0);
            float a1 = ll[(t * 32 + 2 * p + 1) * 2 + 0], b1 = ll[(t * 32 + 2 * p + 1) * 2 + 1];
            float m1 = fmaxf(a1, b1), e1 = expf(a1 - m1), f1 = expf(b1 - m1);
            float i1 = w / (e1 + f1);
            float4 v;
            v.x = e0 * i0; v.y = f0 * i0;
            v.z = e1 * i1 - v.x; v.w = f1 * i1 - v.y;
            cf[p] = v;
        }
    }
    __syncthreads();

    const uint32_t sBu = smem_u32(smem) + SM_B;
    // ldmatrix.x4 lane addressing: quad g = lane/8 -> tiles {nb0 klo, nb0 khi, nb1 klo, nb1 khi}
    const int r8 = lane & 7, gq = lane >> 3;
    const uint32_t lm_off = (uint32_t)(((gq >> 1) * 8 + r8) * B_STRIDE + (gq & 1) * 16);

    const int r0 = lane >> 2;          // frag row within 8
    const int c0 = (lane & 3) * 2;     // frag col pair
    float* sGf = (float*)(smem + SM_G);

    // ---------- tile loop ----------
    for (int tile = blockIdx.x; tile < n_tiles; tile += gridDim.x) {
        // A fragments: warp's 32 rows x K=128 -> 64 bf16x2 regs, reused for all 20 trees.
        const float* xw = x + ((long)tile * TILE_M + warp * 32) * F_DIM;
        uint32_t A[2][8][4];
#pragma unroll
        for (int mb = 0; mb < 2; ++mb)
#pragma unroll
            for (int k = 0; k < 8; ++k)
#pragma unroll
                for (int j = 0; j < 4; ++j) {
                    // a0:(r,c) a1:(r+8,c) a2:(r,c+8) a3:(r+8,c+8)
                    int row = mb * 16 + r0 + 8 * (j & 1);
                    int col = k * 16 + c0 + 8 * (j >> 1);
                    float2 v = *(const float2*)(xw + row * F_DIM + col);
                    __nv_bfloat162 p = __floats2bfloat162_rn(v.x, v.y);
                    A[mb][k][j] = *(uint32_t*)&p;
                }

        float acc0 = 0.f, acc1 = 0.f;

        for (int t = 0; t < T_TREES; ++t) {
            float c[2][4][4];
#pragma unroll
            for (int i = 0; i < 32; ++i) ((float*)c)[i] = 0.f;

            const uint32_t bbase = sBu + t * B_TREE + lm_off;
#pragma unroll
            for (int k = 0; k < 8; ++k) {
                uint32_t b0, b1, b2, b3, b4, b5, b6, b7;
                LDSM_X4(b0, b1, b2, b3, bbase + k * 32);          // nb 0,1
                LDSM_X4(b4, b5, b6, b7, bbase + k * 32 + 4352);   // nb 2,3 (16*272)
#pragma unroll
                for (int mb = 0; mb < 2; ++mb) {
                    MMA_16816(c[mb][0], A[mb][k], b0, b1);
                    MMA_16816(c[mb][1], A[mb][k], b2, b3);
                    MMA_16816(c[mb][2], A[mb][k], b4, b5);
                    MMA_16816(c[mb][3], A[mb][k], b6, b7);
                }
            }

            // sigmoid + transpose via smem (column-major, stride 260 words:
            // write bank (8(lane&3)+(lane>>2)) and read bank (4n+lane) both conflict-free)
            const float* hbt = hb + t * 32;
#pragma unroll
            for (int nb = 0; nb < 4; ++nb) {
                float2 h2 = *(const float2*)(hbt + nb * 8 + c0);
                int n0 = nb * 8 + c0;
#pragma unroll
                for (int mb = 0; mb < 2; ++mb) {
                    int rw = warp * 32 + mb * 16 + r0;
                    sGf[(n0    ) * G_STRIDE + rw    ] = sig_half(c[mb][nb][0], h2.x);
                    sGf[(n0 + 1) * G_STRIDE + rw    ] = sig_half(c[mb][nb][1], h2.y);
                    sGf[(n0    ) * G_STRIDE + rw + 8] = sig_half(c[mb][nb][2], h2.x);
                    sGf[(n0 + 1) * G_STRIDE + rw + 8] = sig_half(c[mb][nb][3], h2.y);
                }
            }
            __syncwarp();   // warp w wrote exactly rows [32w,32w+32) — warp-private

            // per-row bottom-up combine, row = tid
            float g[N_INT];
#pragma unroll
            for (int n = 0; n < N_INT; ++n) g[n] = sGf[n * G_STRIDE + tid];

            const float4* cf = (const float4*)(smem + SM_COEF) + t * 16;
            float p0[16], p1[16];
#pragma unroll
            for (int i = 0; i < 16; ++i) {               // level 4: gates 15..30
                float4 cv = cf[i];
                float gi = g[15 + i];
                p0[i] = fmaf(gi, cv.z, cv.x);
                p1[i] = fmaf(gi, cv.w, cv.y);
            }
#pragma unroll
            for (int i = 0; i < 8; ++i) {                // level 3
                float gi = g[7 + i];
                p0[i] = fmaf(gi, p0[2 * i + 1] - p0[2 * i], p0[2 * i]);
                p1[i] = fmaf(gi, p1[2 * i + 1] - p1[2 * i], p1[2 * i]);
            }
#pragma unroll
            for (int i = 0; i < 4; ++i) {                // level 2
                float gi = g[3 + i];
                p0[i] = fmaf(gi, p0[2 * i + 1] - p0[2 * i], p0[2 * i]);
                p1[i] = fmaf(gi, p1[2 * i + 1] - p1[2 * i], p1[2 * i]);
            }
#pragma unroll
            for (int i = 0; i < 2; ++i) {                // level 1
                float gi = g[1 + i];
                p0[i] = fmaf(gi, p0[2 * i + 1] - p0[2 * i], p0[2 * i]);
                p1[i] = fmaf(gi, p1[2 * i + 1] - p1[2 * i], p1[2 * i]);
            }
            acc0 += fmaf(g[0], p0[1] - p0[0], p0[0]);    // level 0
            acc1 += fmaf(g[0], p1[1] - p1[0], p1[0]);

            __syncwarp();   // before next tree overwrites gates
        }

        ((float2*)out)[(long)tile * TILE_M + tid] = make_float2(acc0, acc1);
    }
}

// ---------------------------------------------------------------------------
// metadata order: x, split_weights, split_bias, leaf_logits, tree_weights,
//                 feature_masks.  output: [B,2] float32
// ---------------------------------------------------------------------------
extern "C" void kernel_launch(void* const* d_in, const int* in_sizes, int n_in,
                              void* d_out, int out_size) {
    const float* x  = (const float*)d_in[0];
    const float* sw = (const float*)d_in[1];
    const float* sb = (const float*)d_in[2];
    const float* ll = (const float*)d_in[3];
    const float* tw = (const float*)d_in[4];
    const float* fm = (const float*)d_in[5];
    float* out = (float*)d_out;

    const int B = in_sizes[0] / F_DIM;     // 131072
    const int n_tiles = B / TILE_M;        // 512

    int nsm = 148;
    cudaDeviceGetAttribute(&nsm, cudaDevAttrMultiProcessorCount, 0);

    cudaFuncSetAttribute(forest_hmma, cudaFuncAttributeMaxDynamicSharedMemorySize, SMEM_TOTAL);
    forest_hmma<<<nsm, THREADS, SMEM_TOTAL>>>(x, sw, sb, ll, tw, fm, out, n_tiles);
}

// round 9
// speedup vs baseline: 8.6237x; 1.1142x over previous
#include <cuda_runtime.h>
#include <cuda_bf16.h>
#include <cuda_fp16.h>
#include <cstdint>

#define T_TREES 20
#define N_INT   31
#define F_DIM   128
#define TILE_M  512
#define THREADS 512            // 16 warps

// ---------------- smem layout (bytes) ----------------
#define B_STRIDE 272                       // 128 bf16 = 256B + 16B pad (ldmatrix conflict-free)
#define B_TREE   (32 * B_STRIDE)           // 8704 per tree
#define SM_B     0
#define SM_G     (T_TREES * B_TREE)                  // 174080
#define G_HSTRIDE 524                                // halves per node column (512 rows + pad)
#define SM_HB    (SM_G + 32 * G_HSTRIDE * 2)         // 207616
#define SM_COEF  (SM_HB + T_TREES * 32 * 4)          // 210176
#define SMEM_TOTAL (SM_COEF + T_TREES * 16 * 16)     // 215296

__device__ __forceinline__ uint32_t smem_u32(const void* p) {
    uint32_t a;
    asm("{ .reg .u64 t; cvta.to.shared.u64 t, %1; cvt.u32.u64 %0, t; }" : "=r"(a) : "l"(p));
    return a;
}

// sigmoid(z) = 0.5*tanh(0.5*z + 0.5*bias) + 0.5  -> one MUFU.TANH
__device__ __forceinline__ float sig_half(float logit, float hb) {
    float z = fmaf(logit, 0.5f, hb);
    float th;
    asm("tanh.approx.f32 %0, %1;" : "=f"(th) : "f"(z));
    return fmaf(th, 0.5f, 0.5f);
}

#define LDSM_X4(d0, d1, d2, d3, addr) \
    asm volatile("ldmatrix.sync.aligned.m8n8.x4.shared.b16 {%0,%1,%2,%3}, [%4];" \
                 : "=r"(d0), "=r"(d1), "=r"(d2), "=r"(d3) : "r"(addr))

#define MMA_16816(c, a, b0v, b1v) \
    asm volatile("mma.sync.aligned.m16n8k16.row.col.f32.bf16.bf16.f32 " \
                 "{%0,%1,%2,%3}, {%4,%5,%6,%7}, {%8,%9}, {%0,%1,%2,%3};" \
                 : "+f"((c)[0]), "+f"((c)[1]), "+f"((c)[2]), "+f"((c)[3]) \
                 : "r"((a)[0]), "r"((a)[1]), "r"((a)[2]), "r"((a)[3]), \
                   "r"(b0v), "r"(b1v))

// ---------------------------------------------------------------------------
// One persistent kernel, 16 warps/CTA, 1 CTA/SM.
// Per tile: A fragments (warp's 32 rows) in regs, reused across 20 trees.
// Gates spilled through smem as fp16 (warp-private region -> __syncwarp only).
// ---------------------------------------------------------------------------
__global__ __launch_bounds__(THREADS, 1)
void forest_hmma(const float* __restrict__ x,  const float* __restrict__ sw,
                 const float* __restrict__ sb, const float* __restrict__ ll,
                 const float* __restrict__ tw, const float* __restrict__ fm,
                 float* __restrict__ out, int n_tiles)
{
    extern __shared__ unsigned char smem[];
    const int tid  = threadIdx.x;
    const int lane = tid & 31;
    const int warp = tid >> 5;

    // ---------- CTA init ----------
    for (int idx = tid; idx < T_TREES * 32 * F_DIM; idx += THREADS) {
        int t = idx >> 12, n = (idx >> 7) & 31, k = idx & 127;
        float v = (n < N_INT) ? sw[(t * N_INT + n) * F_DIM + k] * fm[t * F_DIM + k] : 0.f;
        *(__nv_bfloat16*)(smem + SM_B + t * B_TREE + n * B_STRIDE + k * 2) = __float2bfloat16(v);
    }
    float* hb = (float*)(smem + SM_HB);
    for (int idx = tid; idx < T_TREES * 32; idx += THREADS) {
        int t = idx >> 5, n = idx & 31;
        hb[idx] = (n < N_INT) ? 0.5f * sb[t * N_INT + n] : 0.f;
    }
    if (tid < T_TREES) {
        int t = tid;
        float mx = tw[0];
        for (int i = 1; i < T_TREES; ++i) mx = fmaxf(mx, tw[i]);
        float s = 0.f;
        for (int i = 0; i < T_TREES; ++i) s += expf(tw[i] - mx);
        float w = expf(tw[t] - mx) / s;
        float4* cf = (float4*)(smem + SM_COEF) + t * 16;
        for (int p = 0; p < 16; ++p) {
            float a0 = ll[(t * 32 + 2 * p) * 2 + 0], b0 = ll[(t * 32 + 2 * p) * 2 + 1];
            float m0 = fmaxf(a0, b0), e0 = expf(a0 - m0), f0 = expf(b0 - m0);
            float i0 = w / (e0 + f0);
            float a1 = ll[(t * 32 + 2 * p + 1) * 2 + 0], b1 = ll[(t * 32 + 2 * p + 1) * 2 + 1];
            float m1 = fmaxf(a1, b1), e1 = expf(a1 - m1), f1 = expf(b1 - m1);
            float i1 = w / (e1 + f1);
            float4 v;
            v.x = e0 * i0; v.y = f0 * i0;
            v.z = e1 * i1 - v.x; v.w = f1 * i1 - v.y;
            cf[p] = v;
        }
    }
    __syncthreads();

    const uint32_t sBu = smem_u32(smem) + SM_B;
    const int r8 = lane & 7, gq = lane >> 3;
    const uint32_t lm_off = (uint32_t)(((gq >> 1) * 8 + r8) * B_STRIDE + (gq & 1) * 16);

    const int r0 = lane >> 2;          // frag row within 8
    const int c0 = (lane & 3) * 2;     // frag col pair
    __half* sGh = (__half*)(smem + SM_G);

    // ---------- tile loop ----------
    for (int tile = blockIdx.x; tile < n_tiles; tile += gridDim.x) {
        // A fragments: warp's 32 rows x K=128 -> 64 bf16x2 regs, reused for 20 trees.
        const float* xw = x + ((long)tile * TILE_M + warp * 32) * F_DIM;
        uint32_t A[2][8][4];
#pragma unroll
        for (int mb = 0; mb < 2; ++mb)
#pragma unroll
            for (int k = 0; k < 8; ++k)
#pragma unroll
                for (int j = 0; j < 4; ++j) {
                    int row = mb * 16 + r0 + 8 * (j & 1);
                    int col = k * 16 + c0 + 8 * (j >> 1);
                    float2 v = *(const float2*)(xw + row * F_DIM + col);
                    __nv_bfloat162 p = __floats2bfloat162_rn(v.x, v.y);
                    A[mb][k][j] = *(uint32_t*)&p;
                }

        float acc0 = 0.f, acc1 = 0.f;

        for (int t = 0; t < T_TREES; ++t) {
            float c[2][4][4];
#pragma unroll
            for (int i = 0; i < 32; ++i) ((float*)c)[i] = 0.f;

            const uint32_t bbase = sBu + t * B_TREE + lm_off;
#pragma unroll
            for (int k = 0; k < 8; ++k) {
                uint32_t b0, b1, b2, b3, b4, b5, b6, b7;
                LDSM_X4(b0, b1, b2, b3, bbase + k * 32);          // nodes 0..15
                LDSM_X4(b4, b5, b6, b7, bbase + k * 32 + 4352);   // nodes 16..31
#pragma unroll
                for (int mb = 0; mb < 2; ++mb) {
                    MMA_16816(c[mb][0], A[mb][k], b0, b1);
                    MMA_16816(c[mb][1], A[mb][k], b2, b3);
                    MMA_16816(c[mb][2], A[mb][k], b4, b5);
                    MMA_16816(c[mb][3], A[mb][k], b6, b7);
                }
            }

            // sigmoid + fp16 transpose via smem (column-major over nodes)
            const float* hbt = hb + t * 32;
#pragma unroll
            for (int nb = 0; nb < 4; ++nb) {
                float2 h2 = *(const float2*)(hbt + nb * 8 + c0);
                int n0 = nb * 8 + c0;
#pragma unroll
                for (int mb = 0; mb < 2; ++mb) {
                    int rw = warp * 32 + mb * 16 + r0;
                    sGh[(n0    ) * G_HSTRIDE + rw    ] = __float2half_rn(sig_half(c[mb][nb][0], h2.x));
                    sGh[(n0 + 1) * G_HSTRIDE + rw    ] = __float2half_rn(sig_half(c[mb][nb][1], h2.y));
                    sGh[(n0    ) * G_HSTRIDE + rw + 8] = __float2half_rn(sig_half(c[mb][nb][2], h2.x));
                    sGh[(n0 + 1) * G_HSTRIDE + rw + 8] = __float2half_rn(sig_half(c[mb][nb][3], h2.y));
                }
            }
            __syncwarp();   // warp w wrote exactly rows [32w,32w+32) — warp-private

            // per-row bottom-up combine, row = tid; gates read inline (reg cap 128)
#define GATE(n) __half2float(sGh[(n) * G_HSTRIDE + tid])
            const float4* cf = (const float4*)(smem + SM_COEF) + t * 16;
            float p0[16], p1[16];
#pragma unroll
            for (int i = 0; i < 16; ++i) {               // level 4: gates 15..30
                float4 cv = cf[i];
                float gi = GATE(15 + i);
                p0[i] = fmaf(gi, cv.z, cv.x);
                p1[i] = fmaf(gi, cv.w, cv.y);
            }
#pragma unroll
            for (int i = 0; i < 8; ++i) {                // level 3
                float gi = GATE(7 + i);
                p0[i] = fmaf(gi, p0[2 * i + 1] - p0[2 * i], p0[2 * i]);
                p1[i] = fmaf(gi, p1[2 * i + 1] - p1[2 * i], p1[2 * i]);
            }
#pragma unroll
            for (int i = 0; i < 4; ++i) {                // level 2
                float gi = GATE(3 + i);
                p0[i] = fmaf(gi, p0[2 * i + 1] - p0[2 * i], p0[2 * i]);
                p1[i] = fmaf(gi, p1[2 * i + 1] - p1[2 * i], p1[2 * i]);
            }
#pragma unroll
            for (int i = 0; i < 2; ++i) {                // level 1
                float gi = GATE(1 + i);
                p0[i] = fmaf(gi, p0[2 * i + 1] - p0[2 * i], p0[2 * i]);
                p1[i] = fmaf(gi, p1[2 * i + 1] - p1[2 * i], p1[2 * i]);
            }
            {
                float gi = GATE(0);                      // level 0
                acc0 += fmaf(gi, p0[1] - p0[0], p0[0]);
                acc1 += fmaf(gi, p1[1] - p1[0], p1[0]);
            }
#undef GATE
            __syncwarp();   // before next tree overwrites gates
        }

        ((float2*)out)[(long)tile * TILE_M + tid] = make_float2(acc0, acc1);
    }
}

// ---------------------------------------------------------------------------
// metadata order: x, split_weights, split_bias, leaf_logits, tree_weights,
//                 feature_masks.  output: [B,2] float32
// ---------------------------------------------------------------------------
extern "C" void kernel_launch(void* const* d_in, const int* in_sizes, int n_in,
                              void* d_out, int out_size) {
    const float* x  = (const float*)d_in[0];
    const float* sw = (const float*)d_in[1];
    const float* sb = (const float*)d_in[2];
    const float* ll = (const float*)d_in[3];
    const float* tw = (const float*)d_in[4];
    const float* fm = (const float*)d_in[5];
    float* out = (float*)d_out;

    const int B = in_sizes[0] / F_DIM;     // 131072
    const int n_tiles = B / TILE_M;        // 256

    int nsm = 148;
    cudaDeviceGetAttribute(&nsm, cudaDevAttrMultiProcessorCount, 0);

    cudaFuncSetAttribute(forest_hmma, cudaFuncAttributeMaxDynamicSharedMemorySize, SMEM_TOTAL);
    forest_hmma<<<nsm, THREADS, SMEM_TOTAL>>>(x, sw, sb, ll, tw, fm, out, n_tiles);
}